// round 16
// baseline (speedup 1.0000x reference)
#include <cuda_runtime.h>
#include <math.h>
#include <stdint.h>

#define HID   768
#define BATCH 4
#define SEQ   2048
#define NH    12
#define HD    64
#define MTOT  (BATCH*SEQ)
#define NEG_BIG (-1e31f)

// Scratch: Q,K,V in [B,H,S,hd] (tf32-rounded), plus tf32 copies of toks and W.
__device__ float g_q[BATCH*NH*SEQ*HD];
__device__ float g_k[BATCH*NH*SEQ*HD];
__device__ float g_v[BATCH*NH*SEQ*HD];
__device__ float g_ta[MTOT*HID];        // tf32 toks
__device__ float g_tw[3*HID*HID];       // tf32 Wq|Wk|Wv

// ---------------------------------------------------------------------------
// helpers
// ---------------------------------------------------------------------------
__device__ __forceinline__ uint32_t f2tf(float f) {
    uint32_t u;
    asm("cvt.rna.tf32.f32 %0, %1;" : "=r"(u) : "f"(f));
    return u;
}
__device__ __forceinline__ uint4 tf4(float4 v) {
    uint4 u;
    u.x = f2tf(v.x); u.y = f2tf(v.y); u.z = f2tf(v.z); u.w = f2tf(v.w);
    return u;
}
__device__ __forceinline__ void mma_tf32(float* c, const uint32_t* a,
                                         uint32_t b0, uint32_t b1) {
    asm volatile(
        "mma.sync.aligned.m16n8k8.row.col.f32.tf32.tf32.f32 "
        "{%0,%1,%2,%3},{%4,%5,%6,%7},{%8,%9},{%0,%1,%2,%3};"
        : "+f"(c[0]), "+f"(c[1]), "+f"(c[2]), "+f"(c[3])
        : "r"(a[0]), "r"(a[1]), "r"(a[2]), "r"(a[3]), "r"(b0), "r"(b1));
}
__device__ __forceinline__ uint32_t smem_u32(const void* p) {
    uint32_t a;
    asm("{ .reg .u64 t; cvta.to.shared.u64 t, %1; cvt.u32.u64 %0, t; }"
        : "=r"(a) : "l"(p));
    return a;
}
#define CP16(sa, ga) \
    asm volatile("cp.async.ca.shared.global [%0], [%1], 16;" :: "r"(sa), "l"(ga) : "memory")
#define CP_COMMIT() asm volatile("cp.async.commit_group;" ::: "memory")
#define CP_WAIT1()  asm volatile("cp.async.wait_group 1;" ::: "memory")
#define CP_WAIT0()  asm volatile("cp.async.wait_group 0;" ::: "memory")

// ---------------------------------------------------------------------------
// Kernel 0: pre-convert toks and W to tf32 (RNA) so the GEMM can cp.async raw.
// ---------------------------------------------------------------------------
__global__ __launch_bounds__(256) void conv_kernel(const float* __restrict__ toks,
                                                   const float* __restrict__ Wq,
                                                   const float* __restrict__ Wk,
                                                   const float* __restrict__ Wv) {
    int i = blockIdx.x * blockDim.x + threadIdx.x;      // float4 index
    const int n_t = MTOT * HID / 4;                     // 1,572,864
    const int n_w = HID * HID / 4;                      // 147,456
    if (i < n_t)
        *(uint4*)&g_ta[i * 4] = tf4(((const float4*)toks)[i]);
    if (i < n_w) {
        *(uint4*)&g_tw[i * 4]                 = tf4(((const float4*)Wq)[i]);
        *(uint4*)&g_tw[HID * HID + i * 4]     = tf4(((const float4*)Wk)[i]);
        *(uint4*)&g_tw[2 * HID * HID + i * 4] = tf4(((const float4*)Wv)[i]);
    }
}

// ---------------------------------------------------------------------------
// Kernel 1: fused QKV projection, tf32 mma.sync, cp.async double-buffered.
// Block 128x128, K-stage 32, 24 stages.  256 threads = 8 warps (4M x 2N).
// Inputs are pre-converted tf32 -> staging is pure cp.async (no CVT/STS).
// ---------------------------------------------------------------------------
#define ASTR 36
#define BSTR 136
#define GEMM_SMEM ((2 * (128 * ASTR + 32 * BSTR)) * 4)   // 71,680 B

__global__ __launch_bounds__(256, 2) void qkv_gemm_kernel(
        const float* __restrict__ bq, const float* __restrict__ bk,
        const float* __restrict__ bv) {
    extern __shared__ float smg[];
    float* sA[2] = { smg, smg + 128 * ASTR + 32 * BSTR };
    float* sB[2] = { smg + 128 * ASTR, smg + 2 * 128 * ASTR + 32 * BSTR };

    const int nbk = blockIdx.x;        // 0..17
    const int mb  = blockIdx.y;        // 0..63
    const int tid = threadIdx.x;
    const int warpId = tid >> 5;
    const int lane = tid & 31;
    const int g   = lane >> 2;
    const int tig = lane & 3;
    const int wm  = warpId >> 1;
    const int wn  = warpId & 1;

    const int w  = (nbk * 128) / HID;
    const int nc = (nbk * 128) % HID;
    const float* __restrict__ Wm = g_tw + (size_t)w * HID * HID;
    const float* __restrict__ bsel = (w == 0) ? bq : (w == 1) ? bk : bv;

    const uint32_t aA[2] = { smem_u32(sA[0]), smem_u32(sA[1]) };
    const uint32_t aB[2] = { smem_u32(sB[0]), smem_u32(sB[1]) };

    // stage issue helper (inlined twice): A 128x32, B 32x128 for k-tile s
#define GEMM_ISSUE(s) do {                                                     \
        int bufi = (s) & 1;                                                    \
        int k0 = (s) * 32;                                                     \
        _Pragma("unroll")                                                      \
        for (int i = 0; i < 4; i++) {                                          \
            int idx = tid + i * 256;                                           \
            int r = idx >> 3, cg = idx & 7;                                    \
            CP16(aA[bufi] + (uint32_t)(r * ASTR + cg * 4) * 4,                 \
                 &g_ta[(size_t)(mb * 128 + r) * HID + k0 + cg * 4]);           \
        }                                                                      \
        _Pragma("unroll")                                                      \
        for (int i = 0; i < 4; i++) {                                          \
            int idx = tid + i * 256;                                           \
            int r = idx >> 5, cg = idx & 31;                                   \
            CP16(aB[bufi] + (uint32_t)(r * BSTR + cg * 4) * 4,                 \
                 &Wm[(size_t)(k0 + r) * HID + nc + cg * 4]);                   \
        }                                                                      \
        CP_COMMIT();                                                           \
    } while (0)

    float acc[2][8][4];
#pragma unroll
    for (int mi = 0; mi < 2; mi++)
#pragma unroll
        for (int nb = 0; nb < 8; nb++)
#pragma unroll
            for (int j = 0; j < 4; j++) acc[mi][nb][j] = 0.f;

    GEMM_ISSUE(0);

    for (int s = 0; s < HID / 32; s++) {
        if (s + 1 < HID / 32) { GEMM_ISSUE(s + 1); CP_WAIT1(); }
        else                  { CP_WAIT0(); }
        __syncthreads();

        const float* A = sA[s & 1];
        const float* B = sB[s & 1];
#pragma unroll
        for (int kc = 0; kc < 4; kc++) {
            uint32_t af[2][4];
#pragma unroll
            for (int mi = 0; mi < 2; mi++) {
                int row = wm * 32 + mi * 16;
                af[mi][0] = __float_as_uint(A[(row + g)     * ASTR + kc * 8 + tig]);
                af[mi][1] = __float_as_uint(A[(row + g + 8) * ASTR + kc * 8 + tig]);
                af[mi][2] = __float_as_uint(A[(row + g)     * ASTR + kc * 8 + tig + 4]);
                af[mi][3] = __float_as_uint(A[(row + g + 8) * ASTR + kc * 8 + tig + 4]);
            }
            uint32_t bf[8][2];
#pragma unroll
            for (int nb = 0; nb < 8; nb++) {
                int col = wn * 64 + nb * 8 + g;
                bf[nb][0] = __float_as_uint(B[(kc * 8 + tig)     * BSTR + col]);
                bf[nb][1] = __float_as_uint(B[(kc * 8 + tig + 4) * BSTR + col]);
            }
#pragma unroll
            for (int mi = 0; mi < 2; mi++)
#pragma unroll
                for (int nb = 0; nb < 8; nb++)
                    mma_tf32(acc[mi][nb], af[mi], bf[nb][0], bf[nb][1]);
        }
        __syncthreads();
    }

    float* __restrict__ buf = (w == 0) ? g_q : (w == 1) ? g_k : g_v;
#pragma unroll
    for (int mi = 0; mi < 2; mi++) {
#pragma unroll
        for (int nb = 0; nb < 8; nb++) {
            int n = nc + wn * 64 + nb * 8 + 2 * tig;
            int h = n >> 6;
            int d = n & 63;
            float b0v = bsel[n], b1v = bsel[n + 1];
            int row = mb * 128 + wm * 32 + mi * 16 + g;
            int bb = row >> 11;
            int ss = row & 2047;
            float* dst = &buf[((size_t)(bb * NH + h) * SEQ + ss) * HD + d];
            *(float2*)dst =
                make_float2(__uint_as_float(f2tf(acc[mi][nb][0] + b0v)),
                            __uint_as_float(f2tf(acc[mi][nb][1] + b1v)));
            *(float2*)(dst + 8 * HD) =
                make_float2(__uint_as_float(f2tf(acc[mi][nb][2] + b0v)),
                            __uint_as_float(f2tf(acc[mi][nb][3] + b1v)));
        }
    }
}

// ---------------------------------------------------------------------------
// Kernel 2: flash attention, tf32 mma.sync, 16 q-rows/warp, single K/V buffers
// with staged cp.async overlap (round-15 structure), FORCED 4 blocks/SM via
// __launch_bounds__(128, 4) -> regs capped at 128 (round-14 shows body fits).
// ---------------------------------------------------------------------------
#define KSTR 68
#define VSTR 72
#define PSTR 68
#define ATTN_SMEM ((64 * KSTR + 64 * VSTR + 4 * 16 * PSTR + 64) * 4)

__global__ __launch_bounds__(128, 4) void attn_kernel(const int* __restrict__ masks,
                                                      float* __restrict__ out) {
    extern __shared__ float smem[];
    float* sK  = smem;                       // 64*68
    float* sV  = sK + 64 * KSTR;             // 64*72
    float* sP  = sV + 64 * VSTR;             // 4*16*68
    float* sMk = sP + 4 * 16 * PSTR;         // 64

    const int qt  = blockIdx.x;
    const int h   = blockIdx.y;
    const int b   = blockIdx.z;
    const int tid = threadIdx.x;
    const int w    = tid >> 5;
    const int lane = tid & 31;
    const int g    = lane >> 2;
    const int tig  = lane & 3;

    const size_t bh = (size_t)(b * NH + h) * SEQ;
    const float* __restrict__ Qb = g_q + (bh + qt * 64 + w * 16) * HD;
    const float* __restrict__ Kb = g_k + bh * HD;
    const float* __restrict__ Vb = g_v + bh * HD;
    const int*   __restrict__ mrow = masks + b * SEQ;

    const int sr = tid >> 4;
    const int sc = tid & 15;
    const uint32_t aK = smem_u32(sK);
    const uint32_t aV = smem_u32(sV);

    // pre-issue K_0 (group 0) then V_0 (group 1)
#pragma unroll
    for (int i = 0; i < 8; i++) {
        int r = sr + i * 8;
        CP16(aK + (uint32_t)(r * KSTR + sc * 4) * 4, &Kb[(size_t)r * HD + sc * 4]);
    }
    CP_COMMIT();
#pragma unroll
    for (int i = 0; i < 8; i++) {
        int r = sr + i * 8;
        CP16(aV + (uint32_t)(r * VSTR + sc * 4) * 4, &Vb[(size_t)r * HD + sc * 4]);
    }
    CP_COMMIT();

    uint32_t qa[8][4];
#pragma unroll
    for (int kc = 0; kc < 8; kc++) {
        qa[kc][0] = __float_as_uint(Qb[(size_t)g * HD + kc * 8 + tig]);
        qa[kc][1] = __float_as_uint(Qb[(size_t)(g + 8) * HD + kc * 8 + tig]);
        qa[kc][2] = __float_as_uint(Qb[(size_t)g * HD + kc * 8 + tig + 4]);
        qa[kc][3] = __float_as_uint(Qb[(size_t)(g + 8) * HD + kc * 8 + tig + 4]);
    }
    const float fq0 = (float)mrow[qt * 64 + w * 16 + g];
    const float fq1 = (float)mrow[qt * 64 + w * 16 + g + 8];

    float o[8][4];
#pragma unroll
    for (int nb = 0; nb < 8; nb++)
#pragma unroll
        for (int j = 0; j < 4; j++) o[nb][j] = 0.f;
    float m0 = -3.0e38f, m1 = -3.0e38f, l0 = 0.f, l1 = 0.f;

    float* Pw = sP + w * 16 * PSTR;
    const int NT = SEQ / 64;

    for (int t = 0; t < NT; t++) {
        CP_WAIT1();                          // K_t (oldest group) done
        if (tid < 64) sMk[tid] = (float)mrow[t * 64 + tid];
        __syncthreads();

        // S = Q K^T
        float sacc[8][4];
#pragma unroll
        for (int nb = 0; nb < 8; nb++) {
            float c[4] = {0.f, 0.f, 0.f, 0.f};
#pragma unroll
            for (int kc = 0; kc < 8; kc++) {
                uint32_t b0 = __float_as_uint(sK[(nb * 8 + g) * KSTR + kc * 8 + tig]);
                uint32_t b1 = __float_as_uint(sK[(nb * 8 + g) * KSTR + kc * 8 + tig + 4]);
                mma_tf32(c, qa[kc], b0, b1);
            }
            sacc[nb][0] = c[0]; sacc[nb][1] = c[1];
            sacc[nb][2] = c[2]; sacc[nb][3] = c[3];
        }
        __syncthreads();                     // all warps done reading K_t

        if (t + 1 < NT) {                    // K_{t+1}: overlaps softmax + PV
#pragma unroll
            for (int i = 0; i < 8; i++) {
                int r = sr + i * 8;
                CP16(aK + (uint32_t)(r * KSTR + sc * 4) * 4,
                     &Kb[(size_t)((t + 1) * 64 + r) * HD + sc * 4]);
            }
            CP_COMMIT();
        }

        // scale + mask + online softmax
        float mx0 = -3.0e38f, mx1 = -3.0e38f;
#pragma unroll
        for (int nb = 0; nb < 8; nb++) {
#pragma unroll
            for (int j = 0; j < 2; j++) {
                float fk = sMk[nb * 8 + 2 * tig + j];
                float s0 = sacc[nb][j]     * 0.125f + (1.0f - fq0 * fk) * NEG_BIG;
                float s1 = sacc[nb][2 + j] * 0.125f + (1.0f - fq1 * fk) * NEG_BIG;
                sacc[nb][j] = s0; sacc[nb][2 + j] = s1;
                mx0 = fmaxf(mx0, s0); mx1 = fmaxf(mx1, s1);
            }
        }
        mx0 = fmaxf(mx0, __shfl_xor_sync(0xffffffffu, mx0, 1));
        mx0 = fmaxf(mx0, __shfl_xor_sync(0xffffffffu, mx0, 2));
        mx1 = fmaxf(mx1, __shfl_xor_sync(0xffffffffu, mx1, 1));
        mx1 = fmaxf(mx1, __shfl_xor_sync(0xffffffffu, mx1, 2));

        float mn0 = fmaxf(m0, mx0), mn1 = fmaxf(m1, mx1);
        float corr0 = __expf(m0 - mn0), corr1 = __expf(m1 - mn1);
        m0 = mn0; m1 = mn1;

        float ls0 = 0.f, ls1 = 0.f;
#pragma unroll
        for (int nb = 0; nb < 8; nb++) {
#pragma unroll
            for (int j = 0; j < 2; j++) {
                float p0 = __expf(sacc[nb][j] - m0);
                float p1 = __expf(sacc[nb][2 + j] - m1);
                sacc[nb][j] = p0; sacc[nb][2 + j] = p1;
                ls0 += p0; ls1 += p1;
            }
        }
        ls0 += __shfl_xor_sync(0xffffffffu, ls0, 1);
        ls0 += __shfl_xor_sync(0xffffffffu, ls0, 2);
        ls1 += __shfl_xor_sync(0xffffffffu, ls1, 1);
        ls1 += __shfl_xor_sync(0xffffffffu, ls1, 2);
        l0 = l0 * corr0 + ls0;
        l1 = l1 * corr1 + ls1;
#pragma unroll
        for (int nb = 0; nb < 8; nb++) {
            o[nb][0] *= corr0; o[nb][1] *= corr0;
            o[nb][2] *= corr1; o[nb][3] *= corr1;
        }

        // stage P (warp-private)
#pragma unroll
        for (int nb = 0; nb < 8; nb++) {
            *(float2*)&Pw[g * PSTR + nb * 8 + 2 * tig] =
                make_float2(__uint_as_float(f2tf(sacc[nb][0])),
                            __uint_as_float(f2tf(sacc[nb][1])));
            *(float2*)&Pw[(g + 8) * PSTR + nb * 8 + 2 * tig] =
                make_float2(__uint_as_float(f2tf(sacc[nb][2])),
                            __uint_as_float(f2tf(sacc[nb][3])));
        }
        __syncwarp();

        CP_WAIT1();                          // V_t done (K_{t+1} still pending)
        __syncthreads();

        // O += P @ V
#pragma unroll
        for (int kc = 0; kc < 8; kc++) {
            uint32_t pa[4];
            pa[0] = __float_as_uint(Pw[g * PSTR + kc * 8 + tig]);
            pa[1] = __float_as_uint(Pw[(g + 8) * PSTR + kc * 8 + tig]);
            pa[2] = __float_as_uint(Pw[g * PSTR + kc * 8 + tig + 4]);
            pa[3] = __float_as_uint(Pw[(g + 8) * PSTR + kc * 8 + tig + 4]);
#pragma unroll
            for (int nb = 0; nb < 8; nb++) {
                uint32_t b0 = __float_as_uint(sV[(kc * 8 + tig)     * VSTR + nb * 8 + g]);
                uint32_t b1 = __float_as_uint(sV[(kc * 8 + tig + 4) * VSTR + nb * 8 + g]);
                mma_tf32(o[nb], pa, b0, b1);
            }
        }
        __syncthreads();                     // all warps done reading V_t

        if (t + 1 < NT) {                    // V_{t+1}: overlaps next QK^T
#pragma unroll
            for (int i = 0; i < 8; i++) {
                int r = sr + i * 8;
                CP16(aV + (uint32_t)(r * VSTR + sc * 4) * 4,
                     &Vb[(size_t)((t + 1) * 64 + r) * HD + sc * 4]);
            }
            CP_COMMIT();
        }
    }
    CP_WAIT0();

    float inv0 = 1.0f / l0, inv1 = 1.0f / l1;
    int row0 = qt * 64 + w * 16 + g;
#pragma unroll
    for (int nb = 0; nb < 8; nb++) {
        int d = h * HD + nb * 8 + 2 * tig;
        float* dst0 = &out[((size_t)b * SEQ + row0) * HID + d];
        float* dst1 = &out[((size_t)b * SEQ + row0 + 8) * HID + d];
        *(float2*)dst0 = make_float2(o[nb][0] * inv0, o[nb][1] * inv0);
        *(float2*)dst1 = make_float2(o[nb][2] * inv1, o[nb][3] * inv1);
    }
}

// ---------------------------------------------------------------------------
extern "C" void kernel_launch(void* const* d_in, const int* in_sizes, int n_in,
                              void* d_out, int out_size) {
    const float* toks  = (const float*)d_in[0];
    const int*   masks = (const int*)d_in[1];
    const float* Wq = (const float*)d_in[2];
    const float* bq = (const float*)d_in[3];
    const float* Wk = (const float*)d_in[4];
    const float* bk = (const float*)d_in[5];
    const float* Wv = (const float*)d_in[6];
    const float* bv = (const float*)d_in[7];
    float* out = (float*)d_out;

    cudaFuncSetAttribute(qkv_gemm_kernel, cudaFuncAttributeMaxDynamicSharedMemorySize,
                         GEMM_SMEM);
    cudaFuncSetAttribute(attn_kernel, cudaFuncAttributeMaxDynamicSharedMemorySize,
                         ATTN_SMEM);

    conv_kernel<<<(MTOT * HID / 4 + 255) / 256, 256>>>(toks, Wq, Wk, Wv);
    qkv_gemm_kernel<<<dim3(18, 64), 256, GEMM_SMEM>>>(bq, bk, bv);
    attn_kernel<<<dim3(32, NH, BATCH), 128, ATTN_SMEM>>>(masks, out);
}